// round 16
// baseline (speedup 1.0000x reference)
#include <cuda_runtime.h>
#include <cuda_bf16.h>
#include <math.h>

// Problem dims
#define Bq   512
#define Sq   64
#define Tq   32
#define Eq   512
#define Hq   1024
#define H2q  2048
#define G3H  3072   // 3*H
#define G6H  6144   // 3*2H
#define Vq   128

typedef unsigned long long u64;
typedef unsigned int u32;

// ---------------------------------------------------------------------------
// Scratch (device statics; allocation-free)
// Weight/table/bias arrays live in gate-grouped PERMUTED layout:
//   original row (g*H + j)  ->  permuted row (j/64)*192 + g*64 + (j%64)
// ---------------------------------------------------------------------------
__device__ float g_encA[2][Vq][G3H];        // gi tables (permuted, incl b_ih)
__device__ float g_decA[Vq][G6H];           // decoder gi table (permuted)
__device__ float g_bhe[2][G3H];             // b_hh enc (permuted)
__device__ float g_bhd[G6H];                // b_hh dec (permuted)
__device__ float g_lpart[16][Bq][Vq];       // logits K-split partials
__device__ int   g_tok[Bq];                 // current decoder tokens

// hidden states (ping-pong)
__device__ float g_h_e[2][2][Bq][Hq];                 // [dir][pp][b][h]
__device__ float g_hdec_f[2][Bq][H2q];                // [pp][b][2h]
__device__ __nv_bfloat16 g_hhi_e[2][2][Bq][Hq], g_hlo_e[2][2][Bq][Hq];
__device__ __nv_bfloat16 g_hhi_d[2][Bq][H2q],   g_hlo_d[2][Bq][H2q];

// bf16 hi/lo split weights (recurrent: permuted; fc: natural)
__device__ __nv_bfloat16 g_Whi_e[2][G3H][Hq], g_Wlo_e[2][G3H][Hq];
__device__ __nv_bfloat16 g_Whi_d[G6H][H2q],   g_Wlo_d[G6H][H2q];
__device__ __nv_bfloat16 g_Wfc_hi[Vq][H2q],   g_Wfc_lo[Vq][H2q];

// ---------------------------------------------------------------------------
// Helpers
// ---------------------------------------------------------------------------
__device__ __forceinline__ float sigf(float x) { return 1.0f / (1.0f + __expf(-x)); }

__device__ __forceinline__ u32 smem_u32(const void* p) {
    u32 a;
    asm("{ .reg .u64 t; cvta.to.shared.u64 t, %1; cvt.u32.u64 %0, t; }" : "=r"(a) : "l"(p));
    return a;
}
__device__ __forceinline__ u32 swz(u32 o)   { return o ^ ((o >> 3) & 0x70); }  // 128B rows
__device__ __forceinline__ u32 swz64(u32 o) { return o ^ ((o >> 3) & 0x30); }  // 64B rows

__device__ __forceinline__ void cp16(u32 saddr, const void* gaddr) {
    asm volatile("cp.async.cg.shared.global [%0], [%1], 16;" :: "r"(saddr), "l"(gaddr) : "memory");
}
__device__ __forceinline__ void cp_commit() {
    asm volatile("cp.async.commit_group;" ::: "memory");
}
__device__ __forceinline__ void cp_wait2() {
    asm volatile("cp.async.wait_group 2;" ::: "memory");
}
__device__ __forceinline__ void cp_wait1() {
    asm volatile("cp.async.wait_group 1;" ::: "memory");
}
__device__ __forceinline__ void cp_wait0() {
    asm volatile("cp.async.wait_group 0;" ::: "memory");
}
__device__ __forceinline__ void ldsm4(u32 addr, u32& r0, u32& r1, u32& r2, u32& r3) {
    asm volatile("ldmatrix.sync.aligned.m8n8.x4.shared.b16 {%0,%1,%2,%3}, [%4];"
                 : "=r"(r0), "=r"(r1), "=r"(r2), "=r"(r3) : "r"(addr));
}
__device__ __forceinline__ void mma16816(float* c, const u32* a, u32 b0, u32 b1) {
    asm volatile(
        "mma.sync.aligned.m16n8k16.row.col.f32.bf16.bf16.f32 "
        "{%0,%1,%2,%3}, {%4,%5,%6,%7}, {%8,%9}, {%0,%1,%2,%3};"
        : "+f"(c[0]), "+f"(c[1]), "+f"(c[2]), "+f"(c[3])
        : "r"(a[0]), "r"(a[1]), "r"(a[2]), "r"(a[3]), "r"(b0), "r"(b1));
}

// ---------------------------------------------------------------------------
// Unified prep kernel (ONE launch): weight hi/lo splits + bias permute.
// ---------------------------------------------------------------------------
__global__ __launch_bounds__(256) void prep_kernel(
    const float* __restrict__ Wf, const float* __restrict__ Wb,
    const float* __restrict__ Wd, const float* __restrict__ Wfc,
    const float* __restrict__ bf, const float* __restrict__ bb,
    const float* __restrict__ bd)
{
    int task = blockIdx.y;
    int i = blockIdx.x * 256 + threadIdx.x;

    if (task <= 1) {
        if (i >= G3H * Hq) return;
        const float* w = task ? Wb : Wf;
        int row = i >> 10, col = i & 1023;
        int g = row >> 10, jj = row & 1023;
        int prow = (jj >> 6) * 192 + g * 64 + (jj & 63);
        float x = w[i];
        __nv_bfloat16 h = __float2bfloat16(x);
        size_t o = (size_t)prow * Hq + col;
        g_Whi_e[task][0][o] = h;
        g_Wlo_e[task][0][o] = __float2bfloat16(x - __bfloat162float(h));
    } else if (task == 2) {
        if (i >= G6H * H2q) return;
        int row = i >> 11, col = i & 2047;
        int g = row >> 11, jj = row & 2047;
        int prow = (jj >> 6) * 192 + g * 64 + (jj & 63);
        float x = Wd[i];
        __nv_bfloat16 h = __float2bfloat16(x);
        size_t o = (size_t)prow * H2q + col;
        g_Whi_d[0][o] = h;
        g_Wlo_d[0][o] = __float2bfloat16(x - __bfloat162float(h));
    } else if (task == 3) {
        if (i >= Vq * H2q) return;
        float x = Wfc[i];
        __nv_bfloat16 h = __float2bfloat16(x);
        g_Wfc_hi[0][i] = h;
        g_Wfc_lo[0][i] = __float2bfloat16(x - __bfloat162float(h));
    } else {
        if (i < 2 * G3H) {
            int d = i / G3H, n = i % G3H;
            int g = n >> 10, jj = n & 1023;
            g_bhe[d][(jj >> 6) * 192 + g * 64 + (jj & 63)] = d ? bb[n] : bf[n];
        }
        if (i < G6H) {
            int g = i >> 11, jj = i & 2047;
            g_bhd[(jj >> 6) * 192 + g * 64 + (jj & 63)] = bd[i];
        }
    }
}

// ---------------------------------------------------------------------------
// Projection tables: C[M=128, N] = A[128,512] @ W[N,512]^T + bias[N]
// writes PERMUTED (gate-grouped) layout
// ---------------------------------------------------------------------------
__global__ __launch_bounds__(256) void table_kernel(
    const float* __restrict__ enc_emb, const float* __restrict__ dec_emb,
    const float* __restrict__ Wf, const float* __restrict__ bf,
    const float* __restrict__ Wb, const float* __restrict__ bb,
    const float* __restrict__ Wd, const float* __restrict__ bd)
{
    int z = blockIdx.z;
    const float* A; const float* W; const float* bias; float* out; int N; int H;
    if (z == 0)      { A = enc_emb; W = Wf; bias = bf; out = &g_encA[0][0][0]; N = G3H; H = Hq; }
    else if (z == 1) { A = enc_emb; W = Wb; bias = bb; out = &g_encA[1][0][0]; N = G3H; H = Hq; }
    else             { A = dec_emb; W = Wd; bias = bd; out = &g_decA[0][0];    N = G6H; H = H2q; }

    int bn = blockIdx.x * 64;
    if (bn >= N) return;
    int bm = blockIdx.y * 64;
    const int K = Eq;

    __shared__ float As[16][68];
    __shared__ float Bs[16][68];

    int tid = threadIdx.x;
    int tx = tid & 15, ty = tid >> 4;
    int lr = tid >> 2, lc = tid & 3;

    float acc[4][4];
    #pragma unroll
    for (int i = 0; i < 4; i++)
        #pragma unroll
        for (int j = 0; j < 4; j++) acc[i][j] = 0.f;

    for (int k0 = 0; k0 < K; k0 += 16) {
        float4 a4 = *(const float4*)&A[(bm + lr) * K + k0 + lc * 4];
        float4 w4 = *(const float4*)&W[(bn + lr) * K + k0 + lc * 4];
        As[lc*4+0][lr] = a4.x; As[lc*4+1][lr] = a4.y; As[lc*4+2][lr] = a4.z; As[lc*4+3][lr] = a4.w;
        Bs[lc*4+0][lr] = w4.x; Bs[lc*4+1][lr] = w4.y; Bs[lc*4+2][lr] = w4.z; Bs[lc*4+3][lr] = w4.w;
        __syncthreads();
        #pragma unroll
        for (int k = 0; k < 16; k++) {
            float4 av = *(const float4*)&As[k][ty * 4];
            float4 bv = *(const float4*)&Bs[k][tx * 4];
            float am[4] = {av.x, av.y, av.z, av.w};
            float bm4[4] = {bv.x, bv.y, bv.z, bv.w};
            #pragma unroll
            for (int i = 0; i < 4; i++)
                #pragma unroll
                for (int j = 0; j < 4; j++) acc[i][j] += am[i] * bm4[j];
        }
        __syncthreads();
    }

    #pragma unroll
    for (int i = 0; i < 4; i++) {
        int m = bm + ty * 4 + i;
        #pragma unroll
        for (int j = 0; j < 4; j++) {
            int n = bn + tx * 4 + j;
            int g = n / H, jj = n % H;
            int pn = (jj >> 6) * 192 + g * 64 + (jj & 63);
            out[m * N + pn] = acc[i][j] + bias[n];
        }
    }
}

// ---------------------------------------------------------------------------
// Init: zero encoder ping-0 states, load initial tokens
// ---------------------------------------------------------------------------
__global__ void init_kernel(const int* __restrict__ tgt)
{
    int i = blockIdx.x * 256 + threadIdx.x;   // < 2*512*1024
    if (i < 2 * Bq * Hq) {
        int d = i / (Bq * Hq), off = i % (Bq * Hq);
        (&g_h_e[d][0][0][0])[off] = 0.f;
        (&g_hhi_e[d][0][0][0])[off] = __float2bfloat16(0.f);
        (&g_hlo_e[d][0][0][0])[off] = __float2bfloat16(0.f);
    }
    if (i < Bq) g_tok[i] = tgt[i * Tq + 0];
}

// ---------------------------------------------------------------------------
// Fused GRU step: gh = h @ Wperm^T (bf16x3 mma), then GRU update in epilogue.
// 512 threads / 16 warps, warp tile 32x48 (4x4 warp grid over 128x192 tile).
// 4-stage cp.async pipeline, K-chunk 32 (64B rows, SW64 swizzle),
// ONE __syncthreads per chunk; staging issued 3 chunks ahead inside compute.
// Stage layout (40KB): Ah(8K)|Al(8K)|Bh(12K)|Bl(12K).
// ---------------------------------------------------------------------------
#define STGB 40960
#define NSTG 4
#define GEMM_SMEM (NSTG * STGB + 1024)
#define LDE 196

__global__ __launch_bounds__(512, 1) void gru_step_kernel(int mode, int t,
                                                          const int* __restrict__ src)
{
    extern __shared__ char smraw[];
    u32 raw = smem_u32(smraw);
    u32 base = (raw + 1023) & ~1023u;

    int tid = threadIdx.x, wid = tid >> 5, lane = tid & 31;
    int bx = blockIdx.x, bm = blockIdx.y * 128;

    int K, Ntot, dir = 0;
    const __nv_bfloat16 *pAh, *pAl, *pBh, *pBl;
    const float *tab, *bh, *hprevf;
    float* houtf; __nv_bfloat16 *houthi, *houtlo;
    if (mode == 0) {
        dir = blockIdx.z;
        K = Hq; Ntot = G3H;
        int pp = t & 1, pn = pp ^ 1;
        pAh = &g_hhi_e[dir][pp][0][0]; pAl = &g_hlo_e[dir][pp][0][0];
        pBh = &g_Whi_e[dir][0][0];     pBl = &g_Wlo_e[dir][0][0];
        tab = &g_encA[dir][0][0];      bh  = &g_bhe[dir][0];
        hprevf = &g_h_e[dir][pp][0][0];
        houtf  = &g_h_e[dir][pn][0][0];
        houthi = &g_hhi_e[dir][pn][0][0]; houtlo = &g_hlo_e[dir][pn][0][0];
    } else {
        K = H2q; Ntot = G6H;
        int pp = t & 1, pn = pp ^ 1;
        pAh = &g_hhi_d[pp][0][0]; pAl = &g_hlo_d[pp][0][0];
        pBh = &g_Whi_d[0][0];     pBl = &g_Wlo_d[0][0];
        tab = &g_decA[0][0];      bh  = &g_bhd[0];
        hprevf = &g_hdec_f[pp][0][0];
        houtf  = &g_hdec_f[pn][0][0];
        houthi = &g_hhi_d[pn][0][0]; houtlo = &g_hlo_d[pn][0][0];
    }
    const int Hloc = K;
    const int NC = K / 32;           // K-chunk 32
    int bn = bx * 192;
    pAh += (size_t)bm * K; pAl += (size_t)bm * K;
    pBh += (size_t)bn * K; pBl += (size_t)bn * K;

    // warp tile: 4x4 grid of 32x48
    int m0 = (wid >> 2) * 32;
    int n0 = (wid & 3) * 48;

    float acc[2][6][4];   // [m-atom][n-atom][quad]
    #pragma unroll
    for (int i = 0; i < 2; i++)
        #pragma unroll
        for (int n = 0; n < 6; n++)
            #pragma unroll
            for (int q = 0; q < 4; q++) acc[i][n][q] = 0.f;

    // ---- staging (K-chunk 32: rows of 64B; A 256 rows, B 384 rows) ----
    // per thread: A 2 xfers, B 3 xfers (16B each)
    #define STAGE32(stg, kb) do {                                            \
        u32 sb_ = base + (stg) * STGB;                                       \
        _Pragma("unroll")                                                    \
        for (int p = 0; p < 2; p++) {                                        \
            int u_ = tid + 512 * p; int row_ = u_ >> 2, c_ = u_ & 3;         \
            int r_ = row_ & 127;                                             \
            const __nv_bfloat16* g_ = (row_ < 128 ? pAh : pAl)               \
                                      + (size_t)r_ * K + (kb) + c_ * 8;      \
            cp16(sb_ + (row_ < 128 ? 0u : 8192u) + swz64(r_ * 64 + c_ * 16), g_); \
        }                                                                    \
        _Pragma("unroll")                                                    \
        for (int p = 0; p < 3; p++) {                                        \
            int u_ = tid + 512 * p; int row_ = u_ >> 2, c_ = u_ & 3;         \
            int r_ = (row_ < 192) ? row_ : row_ - 192;                       \
            const __nv_bfloat16* g_ = (row_ < 192 ? pBh : pBl)               \
                                      + (size_t)r_ * K + (kb) + c_ * 8;      \
            cp16(sb_ + (row_ < 192 ? 16384u : 28672u) + swz64(r_ * 64 + c_ * 16), g_); \
        }                                                                    \
    } while (0)

    // prologue: stage chunks 0..2
    STAGE32(0, 0);  cp_commit();
    STAGE32(1, 32); cp_commit();
    STAGE32(2, 64); cp_commit();

    int arow = lane & 15;
    int acol = (lane >> 4) * 16;

    for (int c = 0; c < NC; c++) {
        int rem = NC - 1 - c;
        if (rem >= 2)      cp_wait2();
        else if (rem == 1) cp_wait1();
        else               cp_wait0();
        __syncthreads();

        // stage chunk c+3 (buffer (c+3)%4: last read at chunk c-1, protected
        // by the barrier above); cp.asyncs overlap the mma work below
        if (c + 3 < NC) { STAGE32((c + 3) & 3, (c + 3) * 32); cp_commit(); }

        u32 buf = base + (c & 3) * STGB;

        #pragma unroll
        for (int ks = 0; ks < 2; ks++) {
            int obyte = ks * 32 + acol;
            u32 af[2][2][4];   // [split][m-atom][4]
            u32 bf[2][3][4];   // [split][n16][4]
            #pragma unroll
            for (int i = 0; i < 2; i++) {
                u32 off = swz64((m0 + i * 16 + arow) * 64 + obyte);
                ldsm4(buf + off,         af[0][i][0], af[0][i][1], af[0][i][2], af[0][i][3]);
                ldsm4(buf + 8192 + off,  af[1][i][0], af[1][i][1], af[1][i][2], af[1][i][3]);
            }
            #pragma unroll
            for (int j = 0; j < 3; j++) {
                u32 off = swz64((n0 + j * 16 + arow) * 64 + obyte);
                ldsm4(buf + 16384 + off, bf[0][j][0], bf[0][j][1], bf[0][j][2], bf[0][j][3]);
                ldsm4(buf + 28672 + off, bf[1][j][0], bf[1][j][1], bf[1][j][2], bf[1][j][3]);
            }
            // grouped by split-term: 12 independent mmas per group
            #pragma unroll
            for (int i = 0; i < 2; i++)
                #pragma unroll
                for (int j = 0; j < 3; j++)
                    #pragma unroll
                    for (int q = 0; q < 2; q++)
                        mma16816(acc[i][j * 2 + q], af[0][i], bf[0][j][q], bf[0][j][q + 2]);
            #pragma unroll
            for (int i = 0; i < 2; i++)
                #pragma unroll
                for (int j = 0; j < 3; j++)
                    #pragma unroll
                    for (int q = 0; q < 2; q++)
                        mma16816(acc[i][j * 2 + q], af[0][i], bf[1][j][q], bf[1][j][q + 2]);
            #pragma unroll
            for (int i = 0; i < 2; i++)
                #pragma unroll
                for (int j = 0; j < 3; j++)
                    #pragma unroll
                    for (int q = 0; q < 2; q++)
                        mma16816(acc[i][j * 2 + q], af[1][i], bf[0][j][q], bf[0][j][q + 2]);
        }
    }

    // ---- epilogue: acc -> smem, recombine gate triples, GRU update ----
    __syncthreads();
    float* smf = (float*)smraw;
    {
        int g = lane >> 2, tig = lane & 3;
        #pragma unroll
        for (int i = 0; i < 2; i++) {
            int row = m0 + i * 16 + g;
            #pragma unroll
            for (int n = 0; n < 6; n++) {
                int col = n0 + n * 8 + tig * 2;
                *(float2*)&smf[row * LDE + col]       = make_float2(acc[i][n][0], acc[i][n][1]);
                *(float2*)&smf[(row + 8) * LDE + col] = make_float2(acc[i][n][2], acc[i][n][3]);
            }
        }
    }
    __syncthreads();

    int s_idx = dir ? (Sq - 1 - t) : t;
    // 2 consecutive h-columns per thread: 128 rows x 32 pairs / 512 thr = 8 iters
    #pragma unroll 4
    for (int e = 0; e < 8; e++) {
        int idx = e * 512 + tid;
        int row = idx >> 5;            // 0..127
        int sub = (idx & 31) * 2;      // even col in 0..62
        int b = bm + row;
        int tok = (mode == 0) ? src[b * Sq + s_idx] : g_tok[b];
        const float* gi = tab + (size_t)tok * Ntot + bn;
        float2 gh_r = *(float2*)&smf[row * LDE + sub];
        float2 gh_z = *(float2*)&smf[row * LDE + 64 + sub];
        float2 gh_n = *(float2*)&smf[row * LDE + 128 + sub];
        float2 gi_r = *(const float2*)&gi[sub];
        float2 gi_z = *(const float2*)&gi[64 + sub];
        float2 gi_n = *(const float2*)&gi[128 + sub];
        float2 bh_r = *(const float2*)&bh[bn + sub];
        float2 bh_z = *(const float2*)&bh[bn + 64 + sub];
        float2 bh_n = *(const float2*)&bh[bn + 128 + sub];
        int hcol = bx * 64 + sub;
        size_t ho_off = (size_t)b * Hloc + hcol;
        float2 hp = *(const float2*)&hprevf[ho_off];

        float r0 = sigf(gi_r.x + gh_r.x + bh_r.x);
        float r1 = sigf(gi_r.y + gh_r.y + bh_r.y);
        float z0 = sigf(gi_z.x + gh_z.x + bh_z.x);
        float z1 = sigf(gi_z.y + gh_z.y + bh_z.y);
        float n0v = tanhf(gi_n.x + r0 * (gh_n.x + bh_n.x));
        float n1v = tanhf(gi_n.y + r1 * (gh_n.y + bh_n.y));
        float h0 = (1.f - z0) * n0v + z0 * hp.x;
        float h1 = (1.f - z1) * n1v + z1 * hp.y;

        *(float2*)&houtf[ho_off] = make_float2(h0, h1);
        __nv_bfloat16 hh0 = __float2bfloat16(h0);
        __nv_bfloat16 hh1 = __float2bfloat16(h1);
        __nv_bfloat162 vhi; vhi.x = hh0; vhi.y = hh1;
        __nv_bfloat162 vlo;
        vlo.x = __float2bfloat16(h0 - __bfloat162float(hh0));
        vlo.y = __float2bfloat16(h1 - __bfloat162float(hh1));
        *(__nv_bfloat162*)&houthi[ho_off] = vhi;
        *(__nv_bfloat162*)&houtlo[ho_off] = vlo;
    }
}

// ---------------------------------------------------------------------------
// Concat encoder final states -> decoder h0 (ping 0)
// ---------------------------------------------------------------------------
__global__ void concat_kernel()
{
    int i = blockIdx.x * 256 + threadIdx.x;  // < 512*2048
    int b = i >> 11, j = i & 2047;
    float v = (j < Hq) ? g_h_e[0][0][b][j] : g_h_e[1][0][b][j - Hq];
    g_hdec_f[0][b][j] = v;
    __nv_bfloat16 h = __float2bfloat16(v);
    g_hhi_d[0][b][j] = h;
    g_hlo_d[0][b][j] = __float2bfloat16(v - __bfloat162float(h));
}

// ---------------------------------------------------------------------------
// Logits partials via bf16x3 mma: h[512,2048] @ W_fc[128,2048]^T, K-split x16
// grid (16 ksplit, 4 mtile), tile 128x128, K=128/split (2 chunks of 64)
// ---------------------------------------------------------------------------
#define LOG_SMEM (2 * 65536 + 1024)

__global__ __launch_bounds__(256, 1) void logits_mma_kernel(int t)
{
    extern __shared__ char smraw[];
    u32 raw = smem_u32(smraw);
    u32 base = (raw + 1023) & ~1023u;

    int tid = threadIdx.x, wid = tid >> 5, lane = tid & 31;
    int ks = blockIdx.x;
    int bm = blockIdx.y * 128;
    const int K = H2q;
    int kb0 = ks * 128;
    int pb = (t + 1) & 1;

    const __nv_bfloat16* pAh = &g_hhi_d[pb][0][0] + (size_t)bm * K;
    const __nv_bfloat16* pAl = &g_hlo_d[pb][0][0] + (size_t)bm * K;
    const __nv_bfloat16* pBh = &g_Wfc_hi[0][0];
    const __nv_bfloat16* pBl = &g_Wfc_lo[0][0];

    int m0 = (wid >> 2) * 64;
    int n0 = (wid & 3) * 32;

    float acc[4][4][4];
    #pragma unroll
    for (int i = 0; i < 4; i++)
        #pragma unroll
        for (int n = 0; n < 4; n++)
            #pragma unroll
            for (int q = 0; q < 4; q++) acc[i][n][q] = 0.f;

    #define LSTAGE(stg, kb) do {                                             \
        u32 sb_ = base + (stg) * 65536;                                      \
        _Pragma("unroll")                                                    \
        for (int p = 0; p < 16; p++) {                                       \
            int u_ = tid + 256 * p; int row_ = u_ >> 3, c_ = u_ & 7;         \
            int sec_ = row_ >> 7; int r_ = row_ & 127;                       \
            const __nv_bfloat16* g_ =                                        \
                (sec_ == 0 ? pAh : sec_ == 1 ? pAl : sec_ == 2 ? pBh : pBl)  \
                + (size_t)r_ * K + kb0 + (kb) + c_ * 8;                      \
            cp16(sb_ + sec_ * 16384u + swz(r_ * 128 + c_ * 16), g_);         \
        }                                                                    \
    } while (0)

    LSTAGE(0, 0);
    cp_commit();

    #pragma unroll
    for (int c = 0; c < 2; c++) {
        int s = c & 1;
        __syncthreads();
        if (c == 0) { LSTAGE(1, 64); cp_commit(); cp_wait1(); }
        else        { cp_wait0(); }
        __syncthreads();

        u32 buf = base + s * 65536;
        int arow = lane & 15;
        int acol = (lane >> 4) * 16;

        #pragma unroll
        for (int kss = 0; kss < 4; kss++) {
            int obyte = kss * 32 + acol;
            u32 af[2][4][4];
            u32 bf[2][2][4];
            #pragma unroll
            for (int i = 0; i < 4; i++) {
                u32 off = swz((m0 + i * 16 + arow) * 128 + obyte);
                ldsm4(buf + off,         af[0][i][0], af[0][i][1], af[0][i][2], af[0][i][3]);
                ldsm4(buf + 16384 + off, af[1][i][0], af[1][i][1], af[1][i][2], af[1][i][3]);
            }
            #pragma unroll
            for (int j = 0; j < 2; j++) {
                u32 off = swz((n0 + j * 16 + arow) * 128 + obyte);
                ldsm4(buf + 32768 + off, bf[0][j][0], bf[0][j][1], bf[0][j][2], bf[0][j][3]);
                ldsm4(buf + 49152 + off, bf[1][j][0], bf[1][j][1], bf[1][j][2], bf[1][j][3]);
            }
            #pragma unroll
            for (int i = 0; i < 4; i++)
                #pragma unroll
                for (int j = 0; j < 2; j++)
                    #pragma unroll
                    for (int q = 0; q < 2; q++)
                        mma16816(acc[i][j * 2 + q], af[0][i], bf[0][j][q], bf[0][j][q + 2]);
            #pragma unroll
            for (int i = 0; i < 4; i++)
                #pragma unroll
                for (int j = 0; j < 2; j++)
                    #pragma unroll
                    for (int q = 0; q < 2; q++)
                        mma16816(acc[i][j * 2 + q], af[0][i], bf[1][j][q], bf[1][j][q + 2]);
            #pragma unroll
            for (int i = 0; i < 4; i++)
                #pragma unroll
                for (int j = 0; j < 2; j++)
                    #pragma unroll
                    for (int q = 0; q < 2; q++)
                        mma16816(acc[i][j * 2 + q], af[1][i], bf[0][j][q], bf[0][j][q + 2]);
        }
    }

    int g = lane >> 2, tig = lane & 3;
    #pragma unroll
    for (int i = 0; i < 4; i++) {
        int row0 = bm + m0 + i * 16 + g;
        #pragma unroll
        for (int n = 0; n < 4; n++) {
            int col = n0 + n * 8 + tig * 2;
            *(float2*)&g_lpart[ks][row0][col]     = make_float2(acc[i][n][0], acc[i][n][1]);
            *(float2*)&g_lpart[ks][row0 + 8][col] = make_float2(acc[i][n][2], acc[i][n][3]);
        }
    }
}

// ---------------------------------------------------------------------------
// Reduce partials + bias, write logits, argmax -> g_tok
// ---------------------------------------------------------------------------
__global__ __launch_bounds__(128) void reduce_argmax_kernel(
    const float* __restrict__ bfc, float* __restrict__ out, int t)
{
    int b = blockIdx.x;
    int v = threadIdx.x;
    float s = bfc[v];
    #pragma unroll
    for (int ks = 0; ks < 16; ks++) s += g_lpart[ks][b][v];
    out[((size_t)b * (Tq - 1) + t) * Vq + v] = s;

    __shared__ float sv[128];
    __shared__ int   si[128];
    sv[v] = s; si[v] = v;
    __syncthreads();
    #pragma unroll
    for (int off = 64; off > 0; off >>= 1) {
        if (v < off) {
            float o = sv[v + off]; int oi = si[v + off];
            if (o > sv[v] || (o == sv[v] && oi < si[v])) { sv[v] = o; si[v] = oi; }
        }
        __syncthreads();
    }
    if (v == 0) g_tok[b] = si[0];
}

// ---------------------------------------------------------------------------
extern "C" void kernel_launch(void* const* d_in, const int* in_sizes, int n_in,
                              void* d_out, int out_size)
{
    const int*   src     = (const int*)d_in[0];
    const int*   tgt     = (const int*)d_in[1];
    const float* enc_emb = (const float*)d_in[2];
    const float* dec_emb = (const float*)d_in[3];
    const float* W_ih_f  = (const float*)d_in[4];
    const float* W_hh_f  = (const float*)d_in[5];
    const float* b_ih_f  = (const float*)d_in[6];
    const float* b_hh_f  = (const float*)d_in[7];
    const float* W_ih_b  = (const float*)d_in[8];
    const float* W_hh_b  = (const float*)d_in[9];
    const float* b_ih_b  = (const float*)d_in[10];
    const float* b_hh_b  = (const float*)d_in[11];
    const float* W_ih_d  = (const float*)d_in[12];
    const float* W_hh_d  = (const float*)d_in[13];
    const float* b_ih_d  = (const float*)d_in[14];
    const float* b_hh_d  = (const float*)d_in[15];
    const float* W_fc    = (const float*)d_in[16];
    const float* b_fc    = (const float*)d_in[17];
    float* out = (float*)d_out;

    cudaFuncSetAttribute(gru_step_kernel,
                         cudaFuncAttributeMaxDynamicSharedMemorySize, GEMM_SMEM);
    cudaFuncSetAttribute(logits_mma_kernel,
                         cudaFuncAttributeMaxDynamicSharedMemorySize, LOG_SMEM);

    // ONE prep launch: all weight splits (permuted) + bias permutes
    {
        int gx = (G6H * H2q + 255) / 256;     // 49152, covers largest task
        prep_kernel<<<dim3(gx, 5), 256>>>(W_hh_f, W_hh_b, W_hh_d, W_fc,
                                          b_hh_f, b_hh_b, b_hh_d);
    }

    // Projection tables (permuted), init states/tokens
    table_kernel<<<dim3(96, 2, 3), 256>>>(enc_emb, dec_emb,
                                          W_ih_f, b_ih_f, W_ih_b, b_ih_b, W_ih_d, b_ih_d);
    init_kernel<<<4096, 256>>>(tgt);

    // Bidirectional encoder: fused GEMM+GRU, single wave (128 CTAs)
    for (int t = 0; t < Sq; t++)
        gru_step_kernel<<<dim3(16, 4, 2), 512, GEMM_SMEM>>>(0, t, src);

    // decoder h0 = concat(h_fwd, h_bwd)
    concat_kernel<<<4096, 256>>>();

    // Greedy decoder: fused GEMM+GRU (128 CTAs) + mma logits + argmax
    for (int t = 0; t < Tq - 1; t++) {
        gru_step_kernel<<<dim3(32, 4, 1), 512, GEMM_SMEM>>>(1, t, src);
        logits_mma_kernel<<<dim3(16, 4), 256, LOG_SMEM>>>(t);
        reduce_argmax_kernel<<<Bq, 128>>>(b_fc, out, t);
    }
}